// round 1
// baseline (speedup 1.0000x reference)
#include <cuda_runtime.h>
#include <cstdio>

#define NN 10000
#define BB 4
#define EE 160000
#define CC 64
#define CE 16
#define NR (NN*BB)          // 40000 rows

// ---------------- scratch (device globals; allocation-free) ----------------
__device__ float    g_xp[NR*CC];     // node features after w_n  (current layer)
__device__ float    g_y1[NR*CC];     // layer-1 output
__device__ float    g_asrc[NR];      // xp . (q @ aw_q)
__device__ float    g_adst[NR];      // xp . (k @ aw_k)
__device__ float    g_gate[EE*CC];   // sigmoid(edge_attr @ w_e)
__device__ float    g_escal[EE];     // edge_attr . (w_e @ aw_e) + ab
__device__ unsigned g_aggr[NR*CC];   // encoded-float max accumulator
__device__ float    g_qaw[CC], g_kaw[CC], g_wea[CE];
__device__ float    g_abv;

// order-preserving float<->uint encoding for atomicMax
__device__ __forceinline__ unsigned encf(float f) {
    unsigned u = __float_as_uint(f);
    return (u & 0x80000000u) ? ~u : (u | 0x80000000u);
}
__device__ __forceinline__ float decf(unsigned u) {
    return __uint_as_float((u & 0x80000000u) ? (u & 0x7fffffffu) : ~u);
}
__device__ __forceinline__ float sigmoidf(float x) {
    return 1.0f / (1.0f + __expf(-x));
}

// ---------------- prep: fold attention weights --------------------------
__global__ void prep_kernel(const float* __restrict__ q, const float* __restrict__ k,
                            const float* __restrict__ aw, const float* __restrict__ ab,
                            const float* __restrict__ we) {
    int t = threadIdx.x;  // 64 threads
    float sq = 0.f, sk = 0.f;
    for (int c = 0; c < CC; c++) {
        sq += q[t*CC + c] * aw[c];
        sk += k[t*CC + c] * aw[CC + c];
    }
    g_qaw[t] = sq;
    g_kaw[t] = sk;
    if (t < CE) {
        float s = 0.f;
        for (int c = 0; c < CC; c++) s += we[t*CC + c] * aw[2*CC + c];
        g_wea[t] = s;
    }
    if (t == 0) g_abv = ab[0];
}

// ---------------- node transform: xp = x @ w_n, plus att scalars ---------
// block = 512 threads = 8 rows x 64 channels
__global__ void node_xform_kernel(const float* __restrict__ x, const float* __restrict__ wn) {
    __shared__ float ws[CC*CC];      // 16 KB
    __shared__ float xs[8*CC];       // 2 KB
    __shared__ float wq[16], wk[16];
    int tid = threadIdx.x;
    for (int i = tid; i < CC*CC; i += 512) ws[i] = wn[i];
    int row0 = blockIdx.x * 8;
    int r = tid >> 6, c = tid & 63;
    int row = row0 + r;
    xs[tid] = x[row*CC + c];
    __syncthreads();
    float acc = 0.f;
    #pragma unroll
    for (int kk = 0; kk < CC; kk++) acc += xs[r*CC + kk] * ws[kk*CC + c];
    g_xp[row*CC + c] = acc;
    float pq = acc * g_qaw[c];
    float pk = acc * g_kaw[c];
    #pragma unroll
    for (int o = 16; o; o >>= 1) {
        pq += __shfl_down_sync(0xffffffffu, pq, o);
        pk += __shfl_down_sync(0xffffffffu, pk, o);
    }
    int w = tid >> 5;
    if ((tid & 31) == 0) { wq[w] = pq; wk[w] = pk; }
    __syncthreads();
    if (tid < 8) {
        g_asrc[row0 + tid] = wq[2*tid] + wq[2*tid + 1];
        g_adst[row0 + tid] = wk[2*tid] + wk[2*tid + 1];
    }
}

// ---------------- edge gate: gate = sigmoid(edge_attr @ w_e), e_scal -----
// one warp per edge, block = 256 (8 edges)
__global__ void edge_gate_kernel(const float* __restrict__ eattr, const float* __restrict__ we) {
    __shared__ float wes[CE*CC];   // 4 KB
    __shared__ float weas[CE];
    int tid = threadIdx.x;
    for (int i = tid; i < CE*CC; i += 256) wes[i] = we[i];
    if (tid < CE) weas[tid] = g_wea[tid];
    __syncthreads();
    int e = blockIdx.x * 8 + (tid >> 5);
    int lane = tid & 31;
    float av = (lane < CE) ? eattr[e*CE + lane] : 0.f;
    float acc1 = 0.f, acc2 = 0.f;
    #pragma unroll
    for (int j = 0; j < CE; j++) {
        float aj = __shfl_sync(0xffffffffu, av, j);
        acc1 += aj * wes[j*CC + lane];
        acc2 += aj * wes[j*CC + 32 + lane];
    }
    float sc = (lane < CE) ? av * weas[lane] : 0.f;
    #pragma unroll
    for (int o = 16; o; o >>= 1) sc += __shfl_down_sync(0xffffffffu, sc, o);
    g_gate[e*CC + lane]      = sigmoidf(acc1);
    g_gate[e*CC + 32 + lane] = sigmoidf(acc2);
    if (lane == 0) g_escal[e] = sc + g_abv;
}

// ---------------- clear aggregator ---------------------------------------
__global__ void clear_aggr_kernel() {
    int i = blockIdx.x * 1024 + threadIdx.x;
    g_aggr[i] = 0u;   // sentinel: encoded "below -FLT_MAX"
}

// ---------------- edge aggregate (segment max via RED) -------------------
// one warp per edge, block = 256 (8 edges)
__global__ void edge_aggr_kernel(const int* __restrict__ ei) {
    int e = blockIdx.x * 8 + (threadIdx.x >> 5);
    int lane = threadIdx.x & 31;
    int src = ei[e];
    int dst = ei[EE + e];
    float g1 = g_gate[e*CC + lane];
    float g2 = g_gate[e*CC + 32 + lane];
    float es = g_escal[e];
    #pragma unroll
    for (int b = 0; b < BB; b++) {
        int sr = src*BB + b, dr = dst*BB + b;
        float att = sigmoidf(g_asrc[sr] + g_adst[dr] + es);
        float x1 = g_xp[sr*CC + lane];
        float x2 = g_xp[sr*CC + 32 + lane];
        atomicMax(&g_aggr[dr*CC + lane],      encf(att * x1 * g1));
        atomicMax(&g_aggr[dr*CC + 32 + lane], encf(att * x2 * g2));
    }
}

// ---------------- output: y = leaky(xp + [xp,aggr]@ow + ob) ---------------
// block = 512 = 8 rows x 64 channels
__global__ void node_out_kernel(const float* __restrict__ ow, const float* __restrict__ ob,
                                float* __restrict__ yout) {
    __shared__ float ows[2*CC*CC];   // 32 KB
    __shared__ float xs[8*CC];
    __shared__ float as_[8*CC];
    int tid = threadIdx.x;
    for (int i = tid; i < 2*CC*CC; i += 512) ows[i] = ow[i];
    int row0 = blockIdx.x * 8;
    int r = tid >> 6, c = tid & 63;
    int row = row0 + r;
    float xv = g_xp[row*CC + c];
    xs[tid] = xv;
    unsigned u = g_aggr[row*CC + c];
    as_[tid] = (u == 0u) ? 0.f : decf(u);
    __syncthreads();
    float acc = ob[c];
    #pragma unroll
    for (int kk = 0; kk < CC; kk++) acc += xs[r*CC + kk] * ows[kk*CC + c];
    #pragma unroll
    for (int kk = 0; kk < CC; kk++) acc += as_[r*CC + kk] * ows[(CC + kk)*CC + c];
    float v = xv + acc;
    yout[row*CC + c] = (v > 0.f) ? v : 0.01f * v;
}

// ---------------- host orchestration --------------------------------------
static void run_layer(const float* x, const int* ei, const float* ea,
                      const float* wn, const float* we, const float* q,
                      const float* k, const float* aw, const float* ab,
                      const float* ow, const float* ob, float* yout) {
    prep_kernel<<<1, 64>>>(q, k, aw, ab, we);
    node_xform_kernel<<<NR/8, 512>>>(x, wn);
    edge_gate_kernel<<<EE/8, 256>>>(ea, we);
    clear_aggr_kernel<<<(NR*CC)/1024, 1024>>>();
    edge_aggr_kernel<<<EE/8, 256>>>(ei);
    node_out_kernel<<<NR/8, 512>>>(ow, ob, yout);
}

extern "C" void kernel_launch(void* const* d_in, const int* in_sizes, int n_in,
                              void* d_out, int out_size) {
    const float* X   = (const float*)d_in[0];
    const int*   ei  = (const int*)  d_in[1];
    const float* ea  = (const float*)d_in[2];
    const float* wn1 = (const float*)d_in[3];
    const float* we1 = (const float*)d_in[4];
    const float* q1  = (const float*)d_in[5];
    const float* k1  = (const float*)d_in[6];
    const float* aw1 = (const float*)d_in[7];
    const float* ab1 = (const float*)d_in[8];
    const float* ow1 = (const float*)d_in[9];
    const float* ob1 = (const float*)d_in[10];
    const float* wn2 = (const float*)d_in[11];
    const float* we2 = (const float*)d_in[12];
    const float* q2  = (const float*)d_in[13];
    const float* k2  = (const float*)d_in[14];
    const float* aw2 = (const float*)d_in[15];
    const float* ab2 = (const float*)d_in[16];
    const float* ow2 = (const float*)d_in[17];
    const float* ob2 = (const float*)d_in[18];

    float* y1 = nullptr;
    cudaGetSymbolAddress((void**)&y1, g_y1);

    run_layer(X,  ei, ea, wn1, we1, q1, k1, aw1, ab1, ow1, ob1, y1);
    run_layer(y1, ei, ea, wn2, we2, q2, k2, aw2, ab2, ow2, ob2, (float*)d_out);
}